// round 10
// baseline (speedup 1.0000x reference)
#include <cuda_runtime.h>
#include <cstdint>

#define NB   2048
#define CELL 512
#define NK   30
#define LP   1024
#define NV   80
#define N3K  90

__device__ __forceinline__ float ex2f(float v) {
    float r;
    asm("ex2.approx.ftz.f32 %0, %1;" : "=f"(r) : "f"(v));
    return r;
}

// ---------------------------------------------------------------------------
// Fused kernel: one block per batch row b.  3 CTAs/SM so prologues of some
// CTAs overlap the HBM streaming of others.
// Phase 0: params = exp(x[b] @ W.T + b) -> alpha'/beta'/kappa (shared).
// Phase 1: phi[l] = sum_k alpha'_k * 2^(-beta'_k (kappa_k - l)^2)
// Phase 2: w[v] = sum_l phi[l] * onehots[b,l,v]  -- 671 MB HBM stream.
// ---------------------------------------------------------------------------
#define TB 320   // 20 v-chunks (float4) x 16 row-groups

__global__ void __launch_bounds__(TB, 3) kFused(
    const float* __restrict__ x,  const float* __restrict__ kold,
    const float* __restrict__ oh, const float* __restrict__ tlen,
    const float* __restrict__ W,  const float* __restrict__ bias,
    float* __restrict__ out)
{
    __shared__ __align__(16) float sacc[16][NV];
    __shared__ __align__(16) float sphi[LP + 1];
    __shared__ __align__(16) float sx[CELL];
    __shared__ __align__(16) float sraw[N3K + 6];
    __shared__ __align__(16) float sa[NK];
    __shared__ __align__(16) float sb[NK];
    __shared__ __align__(16) float sk[NK];

    const int b    = blockIdx.x;
    const int t    = threadIdx.x;
    const int warp = t >> 5;
    const int lane = t & 31;

    // ---- Phase 0a: stage x row ----
    {
        const float4* xr = (const float4*)(x + (size_t)b * CELL);
        float4* sx4 = (float4*)sx;
        for (int i = t; i < CELL / 4; i += TB) sx4[i] = xr[i];
    }
    __syncthreads();

    // ---- Phase 0b: 90 dot products, 9 per warp ----
    {
        float accs[9];
        #pragma unroll
        for (int i = 0; i < 9; i++) {
            const int j = warp * 9 + i;
            const float4* wp = (const float4*)(W + (size_t)j * CELL) + lane;
            const float4* sp = (const float4*)sx + lane;
            float4 w0 = wp[0], w1 = wp[32], w2 = wp[64], w3 = wp[96];
            float4 x0 = sp[0], x1 = sp[32], x2 = sp[64], x3 = sp[96];
            float a = w0.x * x0.x;
            a = fmaf(w0.y, x0.y, a); a = fmaf(w0.z, x0.z, a); a = fmaf(w0.w, x0.w, a);
            a = fmaf(w1.x, x1.x, a); a = fmaf(w1.y, x1.y, a);
            a = fmaf(w1.z, x1.z, a); a = fmaf(w1.w, x1.w, a);
            a = fmaf(w2.x, x2.x, a); a = fmaf(w2.y, x2.y, a);
            a = fmaf(w2.z, x2.z, a); a = fmaf(w2.w, x2.w, a);
            a = fmaf(w3.x, x3.x, a); a = fmaf(w3.y, x3.y, a);
            a = fmaf(w3.z, x3.z, a); a = fmaf(w3.w, x3.w, a);
            #pragma unroll
            for (int o = 16; o; o >>= 1)
                a += __shfl_xor_sync(0xffffffffu, a, o);
            accs[i] = a;
        }
        float v = accs[0];
        #pragma unroll
        for (int i = 1; i < 9; i++)
            if (lane == i) v = accs[i];
        if (lane < 9) {
            const int j = warp * 9 + lane;
            sraw[j] = __expf(v + bias[j]);
        }
    }
    __syncthreads();

    // ---- Phase 0c: derive alpha'/beta'/kappa ----
    if (t < NK) {
        const float inv = 1024.0f / tlen[b];
        sa[t] = sraw[t] * inv;
        sb[t] = sraw[NK + t] * 1.4426950408889634f;
        const float kap = kold[b * NK + t] + sraw[2 * NK + t];
        sk[t] = kap;
        out[(size_t)NB * NV + (size_t)b * NK + t] = kap;
    }
    __syncthreads();

    // ---- Phase 1: phi ----
    float* phiout = out + (size_t)NB * NV + (size_t)NB * NK + (size_t)b * (LP + 1);
    for (int l = t; l <= LP; l += TB) {
        const float fl = (float)l;
        float acc = 0.f;
        #pragma unroll
        for (int k = 0; k < NK; k++) {
            const float d = sk[k] - fl;
            const float g = -sb[k] * (d * d);
            acc = fmaf(sa[k], ex2f(g), acc);
        }
        sphi[l] = acc;
        phiout[l] = acc;
    }
    __syncthreads();

    // ---- Phase 2: w streaming (unroll 4 to fit 3 CTAs/SM reg budget) ----
    const int c  = t % 20;
    const int r0 = t / 20;
    const float4* ohb = (const float4*)(oh + (size_t)b * LP * NV) + t;

    float4 a0 = make_float4(0.f, 0.f, 0.f, 0.f);
    float4 a1 = make_float4(0.f, 0.f, 0.f, 0.f);

    #pragma unroll
    for (int j = 0; j < 64; j += 4) {
        float4 v[4];
        #pragma unroll
        for (int u = 0; u < 4; u++)
            v[u] = __ldcs(ohb + (size_t)(j + u) * TB);
        float ph[4];
        #pragma unroll
        for (int u = 0; u < 4; u++)
            ph[u] = sphi[r0 + 16 * (j + u)];
        #pragma unroll
        for (int u = 0; u < 4; u++) {
            float4& a = (u & 1) ? a1 : a0;
            a.x = fmaf(ph[u], v[u].x, a.x);
            a.y = fmaf(ph[u], v[u].y, a.y);
            a.z = fmaf(ph[u], v[u].z, a.z);
            a.w = fmaf(ph[u], v[u].w, a.w);
        }
    }
    a0.x += a1.x; a0.y += a1.y; a0.z += a1.z; a0.w += a1.w;
    ((float4*)&sacc[r0][0])[c] = a0;
    __syncthreads();

    for (int v = t; v < NV; v += TB) {
        float s = 0.f;
        #pragma unroll
        for (int i = 0; i < 16; i++) s += sacc[i][v];
        out[(size_t)b * NV + v] = s;
    }
}

// ---------------------------------------------------------------------------
extern "C" void kernel_launch(void* const* d_in, const int* in_sizes, int n_in,
                              void* d_out, int out_size)
{
    const float* x    = (const float*)d_in[0];
    const float* kold = (n_in > 1) ? (const float*)d_in[1] : nullptr;
    const float* oh   = (n_in > 2) ? (const float*)d_in[2] : nullptr;
    const float* tl   = (n_in > 3) ? (const float*)d_in[3] : nullptr;
    const float* W    = (n_in > 4) ? (const float*)d_in[4] : nullptr;
    const float* bias = (n_in > 5) ? (const float*)d_in[5] : nullptr;

    for (int i = 0; i < n_in; i++) {
        switch (in_sizes[i]) {
            case NB * CELL:            x    = (const float*)d_in[i]; break;
            case NB * NK:              kold = (const float*)d_in[i]; break;
            case NB * LP * NV:         oh   = (const float*)d_in[i]; break;
            case NB:                   tl   = (const float*)d_in[i]; break;
            case N3K * CELL:           W    = (const float*)d_in[i]; break;
            case N3K:                  bias = (const float*)d_in[i]; break;
            default: break;
        }
    }

    float* out = (float*)d_out;
    kFused<<<NB, TB>>>(x, kold, oh, tl, W, bias, out);
}

// round 11
// speedup vs baseline: 1.1845x; 1.1845x over previous
#include <cuda_runtime.h>
#include <cstdint>

#define NB   2048
#define CELL 512
#define NK   30
#define LP   1024
#define NV   80
#define N3K  90

#define TB        320      // 16 row-groups x 20 v-chunks
#define S_STAGES  8
#define ROWS_PC   32       // rows per chunk
#define CB        (ROWS_PC * NV * 4)   // 10240 B per chunk
#define NCHUNK    (LP / ROWS_PC)       // 32

// ---- dynamic smem layout (bytes, all 16B aligned) ----
#define OFF_RING   0
#define OFF_SPHI   (S_STAGES * CB)              // 81920
#define OFF_SACC   (OFF_SPHI + 4112)            // sphi: 1025 floats (+pad)
#define OFF_SX     (OFF_SACC + 16 * NV * 4)     // sacc: 5120
#define OFF_SRAW   (OFF_SX + CELL * 4)          // sx: 2048
#define OFF_SA     (OFF_SRAW + 384)
#define OFF_SB     (OFF_SA + 128)
#define OFF_SK     (OFF_SB + 128)
#define OFF_MBAR   (OFF_SK + 128)               // 8 x (full,empty) x 8B = 128
#define SMEM_TOTAL (OFF_MBAR + 128 + 16)

__device__ __forceinline__ float ex2f(float v) {
    float r; asm("ex2.approx.ftz.f32 %0, %1;" : "=f"(r) : "f"(v)); return r;
}
__device__ __forceinline__ uint32_t s2u(const void* p) {
    uint32_t a;
    asm("{ .reg .u64 t; cvta.to.shared.u64 t, %1; cvt.u32.u64 %0, t; }" : "=r"(a) : "l"(p));
    return a;
}
__device__ __forceinline__ void mbar_init(uint32_t m, uint32_t cnt) {
    asm volatile("mbarrier.init.shared.b64 [%0], %1;" :: "r"(m), "r"(cnt) : "memory");
}
__device__ __forceinline__ void mbar_expect_tx(uint32_t m, uint32_t bytes) {
    asm volatile("mbarrier.arrive.expect_tx.shared.b64 _, [%0], %1;" :: "r"(m), "r"(bytes) : "memory");
}
__device__ __forceinline__ void mbar_arrive(uint32_t m) {
    asm volatile("mbarrier.arrive.shared.b64 _, [%0];" :: "r"(m) : "memory");
}
__device__ __forceinline__ void mbar_wait(uint32_t m, uint32_t parity) {
    asm volatile(
        "{\n\t.reg .pred P;\n\t"
        "WL_%=:\n\t"
        "mbarrier.try_wait.parity.acquire.cta.shared::cta.b64 P, [%0], %1, 0x989680;\n\t"
        "@!P bra WL_%=;\n\t"
        "}" :: "r"(m), "r"(parity) : "memory");
}
__device__ __forceinline__ void bulk_g2s(uint32_t dst, const void* src, uint32_t bytes, uint32_t mbar) {
    asm volatile(
        "cp.async.bulk.shared::cluster.global.mbarrier::complete_tx::bytes [%0], [%1], %2, [%3];"
        :: "r"(dst), "l"(src), "r"(bytes), "r"(mbar) : "memory");
}

// ---------------------------------------------------------------------------
// One block per batch row b.  TMA ring (8 x 10KB) is primed BEFORE the GEMM
// prologue so HBM streams while params/phi are computed.
// ---------------------------------------------------------------------------
__global__ void __launch_bounds__(TB, 2) kFused(
    const float* __restrict__ x,  const float* __restrict__ kold,
    const float* __restrict__ oh, const float* __restrict__ tlen,
    const float* __restrict__ W,  const float* __restrict__ bias,
    float* __restrict__ out)
{
    extern __shared__ __align__(128) char sm[];
    float* sphi = (float*)(sm + OFF_SPHI);
    float (*sacc)[NV] = (float(*)[NV])(sm + OFF_SACC);
    float* sx   = (float*)(sm + OFF_SX);
    float* sraw = (float*)(sm + OFF_SRAW);
    float* sa   = (float*)(sm + OFF_SA);
    float* sb   = (float*)(sm + OFF_SB);
    float* sk   = (float*)(sm + OFF_SK);

    const int b    = blockIdx.x;
    const int t    = threadIdx.x;
    const int warp = t >> 5;
    const int lane = t & 31;

    const uint32_t smem_base = s2u(sm);
    const uint32_t ring_u    = smem_base + OFF_RING;
    const uint32_t mb        = smem_base + OFF_MBAR;
    #define FULLB(s)  (mb + (s) * 16)
    #define EMPTYB(s) (mb + (s) * 16 + 8)

    const char* gsrc = (const char*)(oh + (size_t)b * LP * NV);

    // ---- init barriers, stage x row ----
    if (t == 0) {
        #pragma unroll
        for (int s = 0; s < S_STAGES; s++) { mbar_init(FULLB(s), 1); mbar_init(EMPTYB(s), TB); }
    }
    {
        const float4* xr = (const float4*)(x + (size_t)b * CELL);
        float4* sx4 = (float4*)sx;
        for (int i = t; i < CELL / 4; i += TB) sx4[i] = xr[i];
    }
    __syncthreads();

    // ---- prime the ring: HBM streams during the prologue ----
    if (t == 0) {
        #pragma unroll
        for (int c = 0; c < S_STAGES; c++) {
            mbar_expect_tx(FULLB(c), CB);
            bulk_g2s(ring_u + c * CB, gsrc + (size_t)c * CB, CB, FULLB(c));
        }
    }

    // ---- prologue: 90 dot products, 9 per warp ----
    {
        float accs[9];
        #pragma unroll
        for (int i = 0; i < 9; i++) {
            const int j = warp * 9 + i;
            const float4* wp = (const float4*)(W + (size_t)j * CELL) + lane;
            const float4* sp = (const float4*)sx + lane;
            float4 w0 = wp[0], w1 = wp[32], w2 = wp[64], w3 = wp[96];
            float4 x0 = sp[0], x1 = sp[32], x2 = sp[64], x3 = sp[96];
            float a = w0.x * x0.x;
            a = fmaf(w0.y, x0.y, a); a = fmaf(w0.z, x0.z, a); a = fmaf(w0.w, x0.w, a);
            a = fmaf(w1.x, x1.x, a); a = fmaf(w1.y, x1.y, a);
            a = fmaf(w1.z, x1.z, a); a = fmaf(w1.w, x1.w, a);
            a = fmaf(w2.x, x2.x, a); a = fmaf(w2.y, x2.y, a);
            a = fmaf(w2.z, x2.z, a); a = fmaf(w2.w, x2.w, a);
            a = fmaf(w3.x, x3.x, a); a = fmaf(w3.y, x3.y, a);
            a = fmaf(w3.z, x3.z, a); a = fmaf(w3.w, x3.w, a);
            #pragma unroll
            for (int o = 16; o; o >>= 1)
                a += __shfl_xor_sync(0xffffffffu, a, o);
            accs[i] = a;
        }
        float v = accs[0];
        #pragma unroll
        for (int i = 1; i < 9; i++)
            if (lane == i) v = accs[i];
        if (lane < 9) {
            const int j = warp * 9 + lane;
            sraw[j] = __expf(v + bias[j]);
        }
    }
    __syncthreads();

    if (t < NK) {
        const float inv = 1024.0f / tlen[b];
        sa[t] = sraw[t] * inv;
        sb[t] = sraw[NK + t] * 1.4426950408889634f;
        const float kap = kold[b * NK + t] + sraw[2 * NK + t];
        sk[t] = kap;
        out[(size_t)NB * NV + (size_t)b * NK + t] = kap;
    }
    __syncthreads();

    // ---- phi ----
    float* phiout = out + (size_t)NB * NV + (size_t)NB * NK + (size_t)b * (LP + 1);
    for (int l = t; l <= LP; l += TB) {
        const float fl = (float)l;
        float acc = 0.f;
        #pragma unroll
        for (int k = 0; k < NK; k++) {
            const float d = sk[k] - fl;
            const float g = -sb[k] * (d * d);
            acc = fmaf(sa[k], ex2f(g), acc);
        }
        sphi[l] = acc;
        phiout[l] = acc;
    }
    __syncthreads();

    // ---- streaming consume: 32 chunks of 32 rows ----
    const int r0 = t / 20;           // 0..15
    const int c20 = t % 20;
    const float4* ring4 = (const float4*)(sm + OFF_RING);
    float4 a0 = make_float4(0.f, 0.f, 0.f, 0.f);

    for (int c = 0; c < NCHUNK; c++) {
        const int s = c & (S_STAGES - 1);
        mbar_wait(FULLB(s), (c >> 3) & 1);

        const float4 v0 = ring4[s * (CB / 16) + t];
        const float4 v1 = ring4[s * (CB / 16) + t + TB];
        const float ph0 = sphi[c * ROWS_PC + r0];
        const float ph1 = sphi[c * ROWS_PC + 16 + r0];
        a0.x = fmaf(ph0, v0.x, a0.x); a0.y = fmaf(ph0, v0.y, a0.y);
        a0.z = fmaf(ph0, v0.z, a0.z); a0.w = fmaf(ph0, v0.w, a0.w);
        a0.x = fmaf(ph1, v1.x, a0.x); a0.y = fmaf(ph1, v1.y, a0.y);
        a0.z = fmaf(ph1, v1.z, a0.z); a0.w = fmaf(ph1, v1.w, a0.w);

        mbar_arrive(EMPTYB(s));

        if (t == 0 && c + S_STAGES < NCHUNK) {
            mbar_wait(EMPTYB(s), (c >> 3) & 1);   // all 320 consumed this stage
            mbar_expect_tx(FULLB(s), CB);
            bulk_g2s(ring_u + s * CB, gsrc + (size_t)(c + S_STAGES) * CB, CB, FULLB(s));
        }
    }

    ((float4*)&sacc[r0][0])[c20] = a0;
    __syncthreads();

    for (int v = t; v < NV; v += TB) {
        float ssum = 0.f;
        #pragma unroll
        for (int i = 0; i < 16; i++) ssum += sacc[i][v];
        out[(size_t)b * NV + v] = ssum;
    }
}

// ---------------------------------------------------------------------------
extern "C" void kernel_launch(void* const* d_in, const int* in_sizes, int n_in,
                              void* d_out, int out_size)
{
    const float* x    = (const float*)d_in[0];
    const float* kold = (n_in > 1) ? (const float*)d_in[1] : nullptr;
    const float* oh   = (n_in > 2) ? (const float*)d_in[2] : nullptr;
    const float* tl   = (n_in > 3) ? (const float*)d_in[3] : nullptr;
    const float* W    = (n_in > 4) ? (const float*)d_in[4] : nullptr;
    const float* bias = (n_in > 5) ? (const float*)d_in[5] : nullptr;

    for (int i = 0; i < n_in; i++) {
        switch (in_sizes[i]) {
            case NB * CELL:            x    = (const float*)d_in[i]; break;
            case NB * NK:              kold = (const float*)d_in[i]; break;
            case NB * LP * NV:         oh   = (const float*)d_in[i]; break;
            case NB:                   tl   = (const float*)d_in[i]; break;
            case N3K * CELL:           W    = (const float*)d_in[i]; break;
            case N3K:                  bias = (const float*)d_in[i]; break;
            default: break;
        }
    }

    cudaFuncSetAttribute(kFused, cudaFuncAttributeMaxDynamicSharedMemorySize, SMEM_TOTAL);
    float* out = (float*)d_out;
    kFused<<<NB, TB, SMEM_TOTAL>>>(x, kold, oh, tl, W, bias, out);
}